// round 6
// baseline (speedup 1.0000x reference)
#include <cuda_runtime.h>

// ConvKB: score[e] = sum_{c,d} relu(w0c*u_d + w1c*v_d + w2c*r_d + bc) * lw[c,d] + lb
// E=50000, D=128, C=32. Packed f32x2 FMA (d-pairs), dup-packed conv params in regs,
// cp.async double-buffered smem staging of gathered rows (1x L2 traffic, latency
// pipelined), warp = 8 channels x full D, 4-way atomicAdd into pre-initialized out.

#define D 128
#define THREADS 128
#define BLOCKS 444            // 148 SMs * 3 blocks
#define NEDGE 50000
#define EPI 2                 // edges per iteration per block

typedef unsigned long long ull;

__device__ int g_is64;        // 1 if index arrays are int64, 0 if int32

__device__ __forceinline__ ull ffma2(ull a, ull b, ull c) {
    ull d;
    asm("fma.rn.f32x2 %0, %1, %2, %3;" : "=l"(d) : "l"(a), "l"(b), "l"(c));
    return d;
}
__device__ __forceinline__ ull fadd2(ull a, ull b) {
    ull d;
    asm("add.rn.f32x2 %0, %1, %2;" : "=l"(d) : "l"(a), "l"(b));
    return d;
}
// 2*relu(a) packed: a + |a|
__device__ __forceinline__ ull relu2x2(ull a) {
    return fadd2(a, a & 0x7FFFFFFF7FFFFFFFULL);
}
__device__ __forceinline__ ull pack2(float lo, float hi) {
    ull d;
    asm("mov.b64 %0, {%1, %2};" : "=l"(d) : "f"(lo), "f"(hi));
    return d;
}
__device__ __forceinline__ float2 unpack2(ull v) {
    float2 r;
    asm("mov.b64 {%0, %1}, %2;" : "=f"(r.x), "=f"(r.y) : "l"(v));
    return r;
}
__device__ __forceinline__ void cp16(unsigned int dst, const void* src) {
    asm volatile("cp.async.cg.shared.global [%0], [%1], 16;" :: "r"(dst), "l"(src));
}
__device__ __forceinline__ void cp_commit() {
    asm volatile("cp.async.commit_group;");
}
__device__ __forceinline__ void cp_wait_all() {
    asm volatile("cp.async.wait_group 0;");
}

// Fused: dtype detection (thread 0) + out[] init to lin_b.
__global__ void init_kernel(float* __restrict__ out, const float* __restrict__ lin_b,
                            const int* __restrict__ ei) {
    int i = blockIdx.x * blockDim.x + threadIdx.x;
    if (i == 0) {
        int is64 = 1;
        for (int k = 1; k < 128; k += 2)
            if (ei[k] != 0) { is64 = 0; break; }
        g_is64 = is64;
    }
    if (i < NEDGE) out[i] = lin_b[0];
}

__global__ void __launch_bounds__(THREADS, 3) convkb_kernel(
    const float* __restrict__ h,
    const float* __restrict__ g,
    const int* __restrict__ edge_idx,    // [2,E], low int32 words read
    const int* __restrict__ edge_type,   // [E]
    const float* __restrict__ conv_w,    // [C,3]
    const float* __restrict__ conv_b,    // [C]
    const float* __restrict__ lin_w,     // [C*D]
    float* __restrict__ out)             // [E], pre-initialized to lin_b
{
    // sbuf[buf][edge*384 + tensor*128 + d]; tensor: 0=u(head) 1=v(tail) 2=r(rel)
    __shared__ alignas(16) float sbuf[2][EPI * 3 * D];
    __shared__ int sidx[4][EPI][3];      // idx ring: [slot][edge][row,col,rel]

    const int tid  = threadIdx.x;
    const int lane = tid & 31;
    const int warp = tid >> 5;
    const int G    = (int)gridDim.x;
    const int stride = g_is64 ? 2 : 1;

    // ---- Edge-invariant register state (warp covers channels cb..cb+7, all d) ----
    const int cb = warp * 8;
    ull w0d[8], w1d[8], w2d[8], bd[8], lwr[8][2];
    {
        const float2* lw2 = (const float2*)lin_w;
#pragma unroll
        for (int ch = 0; ch < 8; ++ch) {
            int c = cb + ch;
            float a0 = conv_w[3 * c + 0], a1 = conv_w[3 * c + 1], a2 = conv_w[3 * c + 2];
            float bb = conv_b[c];
            w0d[ch] = pack2(a0, a0);
            w1d[ch] = pack2(a1, a1);
            w2d[ch] = pack2(a2, a2);
            bd[ch]  = pack2(bb, bb);
            float2 A = lw2[c * 64 + lane];        // d = 2*lane, 2*lane+1
            float2 B = lw2[c * 64 + lane + 32];   // d = 2*lane+64, 2*lane+65
            lwr[ch][0] = pack2(0.5f * A.x, 0.5f * A.y);   // relu trick: lw pre-scaled
            lwr[ch][1] = pack2(0.5f * B.x, 0.5f * B.y);
        }
    }

    const int iters = (NEDGE + EPI * G - 1) / (EPI * G);

    // ---- Prologue: index slots for iters 0..2 ----
    if (tid < 18) {
        int slot = tid / 6, w = tid % 6, j = w / 3, which = w % 3;
        int e = EPI * (blockIdx.x + slot * G) + j;
        if (e >= NEDGE) e = NEDGE - 1;               // clamp: safe addr, result discarded
        int val = (which == 0) ? edge_idx[(size_t)stride * e]
                : (which == 1) ? edge_idx[(size_t)stride * (NEDGE + e)]
                               : edge_type[(size_t)stride * e];
        sidx[slot][j][which] = val;
    }
    __syncthreads();

    // ---- Stage iter 0 into buf 0 ----
    {
        unsigned int sb = (unsigned int)__cvta_generic_to_shared(&sbuf[0][0]);
        for (int u = tid; u < EPI * 96; u += THREADS) {
            int j = u / 96, rem = u % 96, tens = rem / 32, chunk = rem % 32;
            int idx = sidx[0][j][tens];
            const float* src = ((tens < 2) ? h : g) + (size_t)idx * D + chunk * 4;
            cp16(sb + (unsigned int)(j * 384 + tens * 128 + chunk * 4) * 4u, src);
        }
    }
    cp_commit();

    for (int i = 0; i < iters; ++i) {
        const int b = i & 1;
        cp_wait_all();
        __syncthreads();        // buf[b] data visible to all; buf[b^1] free

        // Stage iter i+1 into buf[b^1]
        if (i + 1 < iters) {
            int slot = (i + 1) & 3;
            unsigned int sb = (unsigned int)__cvta_generic_to_shared(&sbuf[b ^ 1][0]);
            for (int u = tid; u < EPI * 96; u += THREADS) {
                int j = u / 96, rem = u % 96, tens = rem / 32, chunk = rem % 32;
                int idx = sidx[slot][j][tens];
                const float* src = ((tens < 2) ? h : g) + (size_t)idx * D + chunk * 4;
                cp16(sb + (unsigned int)(j * 384 + tens * 128 + chunk * 4) * 4u, src);
            }
        }
        cp_commit();

        // Stage indices for iter i+3
        if (i + 3 < iters && tid < 6) {
            int j = tid / 3, which = tid % 3;
            int e = EPI * (blockIdx.x + (i + 3) * G) + j;
            if (e >= NEDGE) e = NEDGE - 1;
            int val = (which == 0) ? edge_idx[(size_t)stride * e]
                    : (which == 1) ? edge_idx[(size_t)stride * (NEDGE + e)]
                                   : edge_type[(size_t)stride * e];
            sidx[(i + 3) & 3][j][which] = val;
        }

        // ---- Compute both edges from buf[b] ----
        const int eBase = EPI * (blockIdx.x + i * G);
#pragma unroll
        for (int j = 0; j < EPI; ++j) {
            const ull* Bp = (const ull*)(sbuf[b] + j * 384);
            ull u0 = Bp[lane],       u1 = Bp[lane + 32];
            ull v0 = Bp[lane + 64],  v1 = Bp[lane + 96];
            ull r0 = Bp[lane + 128], r1 = Bp[lane + 160];

            ull acc0 = 0ULL, acc1 = 0ULL;
#pragma unroll
            for (int ch = 0; ch < 8; ++ch) {
                ull t0 = ffma2(w2d[ch], r0, bd[ch]);
                ull t1 = ffma2(w2d[ch], r1, bd[ch]);
                t0 = ffma2(w1d[ch], v0, t0);
                t1 = ffma2(w1d[ch], v1, t1);
                t0 = ffma2(w0d[ch], u0, t0);
                t1 = ffma2(w0d[ch], u1, t1);
                t0 = relu2x2(t0);
                t1 = relu2x2(t1);
                acc0 = ffma2(t0, lwr[ch][0], acc0);
                acc1 = ffma2(t1, lwr[ch][1], acc1);
            }
            float2 a = unpack2(fadd2(acc0, acc1));
            float s = a.x + a.y;
#pragma unroll
            for (int off = 16; off > 0; off >>= 1)
                s += __shfl_xor_sync(0xffffffffu, s, off);
            int e = eBase + j;
            if (e < NEDGE && lane == 0)
                atomicAdd(out + e, s);
        }
    }
}

extern "C" void kernel_launch(void* const* d_in, const int* in_sizes, int n_in,
                              void* d_out, int out_size) {
    // Identify inputs by unique element counts (immune to metadata ordering).
    const float *h = 0, *g = 0, *conv_w = 0, *conv_b = 0, *lin_w = 0, *lin_b = 0;
    const int *edge_idx = 0, *edge_type = 0;
    for (int i = 0; i < n_in; ++i) {
        switch (in_sizes[i]) {
            case NEDGE * 128: h         = (const float*)d_in[i]; break;
            case 500 * 128:   g         = (const float*)d_in[i]; break;
            case 2 * NEDGE:   edge_idx  = (const int*)d_in[i];   break;
            case NEDGE:       edge_type = (const int*)d_in[i];   break;
            case 96:          conv_w    = (const float*)d_in[i]; break;
            case 32:          conv_b    = (const float*)d_in[i]; break;
            case 4096:        lin_w     = (const float*)d_in[i]; break;
            case 1:           lin_b     = (const float*)d_in[i]; break;
            default: break;
        }
    }
    float* out = (float*)d_out;

    init_kernel<<<(NEDGE + 255) / 256, 256>>>(out, lin_b, edge_idx);
    convkb_kernel<<<BLOCKS, THREADS>>>(h, g, edge_idx, edge_type,
                                       conv_w, conv_b, lin_w, out);
}

// round 7
// speedup vs baseline: 1.0801x; 1.0801x over previous
#include <cuda_runtime.h>

// ConvKB: score[e] = sum_{c,d} relu(w0c*u_d + w1c*v_d + w2c*r_d + bc) * lw[c,d] + lb
// fp32-lane-throughput bound (~64 FMA lanes/SM/cyc). Conv via packed FFMA2 (3/pair),
// relu moved to ALU pipe (t & ~(t>>31) per word), dot via scalar FFMA on halves.
// Direct LDG.64 gathers (naturally packed), conv weights in regs, lw in smem.

#define D 128
#define THREADS 128
#define BLOCKS 592            // 148 SMs * 4 blocks
#define NEDGE 50000

typedef unsigned long long ull;

__device__ int g_is64;        // 1 if index arrays are int64, 0 if int32

__device__ __forceinline__ ull ffma2(ull a, ull b, ull c) {
    ull d;
    asm("fma.rn.f32x2 %0, %1, %2, %3;" : "=l"(d) : "l"(a), "l"(b), "l"(c));
    return d;
}
__device__ __forceinline__ ull pack2(float lo, float hi) {
    ull d;
    asm("mov.b64 %0, {%1, %2};" : "=l"(d) : "f"(lo), "f"(hi));
    return d;
}
// relu of one fp32 word on the ALU pipe: t & ~(t >> 31)
__device__ __forceinline__ float relu_alu(int w) {
    return __int_as_float(w & ~(w >> 31));
}

// Fused: dtype detection (thread 0) + out[] init to lin_b.
__global__ void init_kernel(float* __restrict__ out, const float* __restrict__ lin_b,
                            const int* __restrict__ ei) {
    int i = blockIdx.x * blockDim.x + threadIdx.x;
    if (i == 0) {
        int is64 = 1;
        for (int k = 1; k < 128; k += 2)
            if (ei[k] != 0) { is64 = 0; break; }
        g_is64 = is64;
    }
    if (i < NEDGE) out[i] = lin_b[0];
}

__global__ void __launch_bounds__(THREADS, 4) convkb_kernel(
    const float* __restrict__ h,
    const float* __restrict__ g,
    const int* __restrict__ edge_idx,    // [2,E], low int32 words read
    const int* __restrict__ edge_type,   // [E]
    const float* __restrict__ conv_w,    // [C,3]
    const float* __restrict__ conv_b,    // [C]
    const float* __restrict__ lin_w,     // [C*D]
    float* __restrict__ out)             // [E], pre-initialized to lin_b
{
    __shared__ alignas(16) float slw[32 * D];   // full lin_w, 16KB

    const int tid  = threadIdx.x;
    const int lane = tid & 31;
    const int warp = tid >> 5;

    // Stage lin_w into smem (float4 granularity).
    {
        const float4* src = (const float4*)lin_w;
        float4* dst = (float4*)slw;
#pragma unroll
        for (int k = 0; k < (32 * D / 4) / THREADS; ++k)
            dst[tid + k * THREADS] = src[tid + k * THREADS];
    }

    // Warp covers channels cb..cb+7, all d. Dup-packed conv params in regs.
    const int cb = warp * 8;
    ull w0d[8], w1d[8], w2d[8], bd[8];
#pragma unroll
    for (int ch = 0; ch < 8; ++ch) {
        int c = cb + ch;
        float a0 = conv_w[3 * c + 0], a1 = conv_w[3 * c + 1], a2 = conv_w[3 * c + 2];
        float bb = conv_b[c];
        w0d[ch] = pack2(a0, a0);
        w1d[ch] = pack2(a1, a1);
        w2d[ch] = pack2(a2, a2);
        bd[ch]  = pack2(bb, bb);
    }
    __syncthreads();

    const int stride = g_is64 ? 2 : 1;
    const int nw = BLOCKS;                  // warps per channel-slice = #blocks
    const int widx = (int)blockIdx.x;       // this warp's index within its slice
    const float2* slw2 = (const float2*)slw;

    for (int e = widx; e < NEDGE; e += nw) {
        const int row = edge_idx[(size_t)stride * e];
        const int col = edge_idx[(size_t)stride * (NEDGE + e)];
        const int rel = edge_type[(size_t)stride * e];

        // Naturally packed d-pairs: lane L holds d=(2L,2L+1) and (2L+64,2L+65).
        const ull* up = (const ull*)(h + (size_t)row * D);
        const ull* vp = (const ull*)(h + (size_t)col * D);
        const ull* rp = (const ull*)(g + (size_t)rel * D);
        ull u0 = up[lane], u1 = up[lane + 32];
        ull v0 = vp[lane], v1 = vp[lane + 32];
        ull r0 = rp[lane], r1 = rp[lane + 32];

        float acc0 = 0.f, acc1 = 0.f, acc2 = 0.f, acc3 = 0.f;
#pragma unroll
        for (int ch = 0; ch < 8; ++ch) {
            // conv: 3 packed FFMA2 per d-pair (fp32 pipe)
            ull t0 = ffma2(w2d[ch], r0, bd[ch]);
            ull t1 = ffma2(w2d[ch], r1, bd[ch]);
            t0 = ffma2(w1d[ch], v0, t0);
            t1 = ffma2(w1d[ch], v1, t1);
            t0 = ffma2(w0d[ch], u0, t0);
            t1 = ffma2(w0d[ch], u1, t1);
            // relu on ALU pipe, dot on scalar FFMA halves
            float y00 = relu_alu((int)(unsigned)t0);
            float y01 = relu_alu((int)(t0 >> 32));
            float y10 = relu_alu((int)(unsigned)t1);
            float y11 = relu_alu((int)(t1 >> 32));
            int c = cb + ch;
            float2 lwa = slw2[c * 64 + lane];        // lw[c, 2L], lw[c, 2L+1]
            float2 lwb = slw2[c * 64 + lane + 32];   // lw[c, 2L+64], lw[c, 2L+65]
            acc0 = fmaf(y00, lwa.x, acc0);
            acc1 = fmaf(y01, lwa.y, acc1);
            acc2 = fmaf(y10, lwb.x, acc2);
            acc3 = fmaf(y11, lwb.y, acc3);
        }
        float s = (acc0 + acc1) + (acc2 + acc3);
#pragma unroll
        for (int off = 16; off > 0; off >>= 1)
            s += __shfl_xor_sync(0xffffffffu, s, off);
        if (lane == 0)
            atomicAdd(out + e, s);
    }
}

extern "C" void kernel_launch(void* const* d_in, const int* in_sizes, int n_in,
                              void* d_out, int out_size) {
    // Identify inputs by unique element counts (immune to metadata ordering).
    const float *h = 0, *g = 0, *conv_w = 0, *conv_b = 0, *lin_w = 0, *lin_b = 0;
    const int *edge_idx = 0, *edge_type = 0;
    for (int i = 0; i < n_in; ++i) {
        switch (in_sizes[i]) {
            case NEDGE * 128: h         = (const float*)d_in[i]; break;
            case 500 * 128:   g         = (const float*)d_in[i]; break;
            case 2 * NEDGE:   edge_idx  = (const int*)d_in[i];   break;
            case NEDGE:       edge_type = (const int*)d_in[i];   break;
            case 96:          conv_w    = (const float*)d_in[i]; break;
            case 32:          conv_b    = (const float*)d_in[i]; break;
            case 4096:        lin_w     = (const float*)d_in[i]; break;
            case 1:           lin_b     = (const float*)d_in[i]; break;
            default: break;
        }
    }
    float* out = (float*)d_out;

    init_kernel<<<(NEDGE + 255) / 256, 256>>>(out, lin_b, edge_idx);
    convkb_kernel<<<BLOCKS, THREADS>>>(h, g, edge_idx, edge_type,
                                       conv_w, conv_b, lin_w, out);
}

// round 8
// speedup vs baseline: 1.1082x; 1.0260x over previous
#include <cuda_runtime.h>

// ConvKB: score[e] = sum_{c,d} relu(w0c*u_d + w1c*v_d + w2c*r_d + bc) * lw[c,d] + lb
// Warp = (edge, 8 channels, all 128 d). All params register-resident, zero smem/sync
// in loop, 3x LDG.128 gathers per warp, packed f32x2 FMA, relu via (t+|t|) with lw
// pre-scaled 0.5, warp shuffle reduce + 4-way atomicAdd into out pre-init to lin_b.

#define D 128
#define THREADS 128
#define BLOCKS 592            // 148 SMs * 4 blocks
#define NEDGE 50000

typedef unsigned long long ull;

__device__ int g_is64;        // 1 if index arrays are int64, 0 if int32

__device__ __forceinline__ ull ffma2(ull a, ull b, ull c) {
    ull d;
    asm("fma.rn.f32x2 %0, %1, %2, %3;" : "=l"(d) : "l"(a), "l"(b), "l"(c));
    return d;
}
__device__ __forceinline__ ull fadd2(ull a, ull b) {
    ull d;
    asm("add.rn.f32x2 %0, %1, %2;" : "=l"(d) : "l"(a), "l"(b));
    return d;
}
// 2*relu(a) packed: a + |a|  (1 LOP3 alu + 1 add fma-pipe)
__device__ __forceinline__ ull relu2x2(ull a) {
    return fadd2(a, a & 0x7FFFFFFF7FFFFFFFULL);
}
__device__ __forceinline__ ull pack2(float lo, float hi) {
    ull d;
    asm("mov.b64 %0, {%1, %2};" : "=l"(d) : "f"(lo), "f"(hi));
    return d;
}
__device__ __forceinline__ float2 unpack2(ull v) {
    float2 r;
    asm("mov.b64 {%0, %1}, %2;" : "=f"(r.x), "=f"(r.y) : "l"(v));
    return r;
}

// Fused: dtype detection (thread 0) + out[] init to lin_b.
__global__ void init_kernel(float* __restrict__ out, const float* __restrict__ lin_b,
                            const int* __restrict__ ei) {
    int i = blockIdx.x * blockDim.x + threadIdx.x;
    if (i == 0) {
        int is64 = 1;
        for (int k = 1; k < 128; k += 2)
            if (ei[k] != 0) { is64 = 0; break; }
        g_is64 = is64;
    }
    if (i < NEDGE) out[i] = lin_b[0];
}

__global__ void __launch_bounds__(THREADS, 4) convkb_kernel(
    const float* __restrict__ h,
    const float* __restrict__ g,
    const int* __restrict__ edge_idx,    // [2,E], low int32 words read
    const int* __restrict__ edge_type,   // [E]
    const float* __restrict__ conv_w,    // [C,3]
    const float* __restrict__ conv_b,    // [C]
    const float* __restrict__ lin_w,     // [C*D]
    float* __restrict__ out)             // [E], pre-initialized to lin_b
{
    const int lane = threadIdx.x & 31;
    const int warp = threadIdx.x >> 5;

    // ---- Edge-invariant register state: warp covers channels cb..cb+7 ----
    // Lane L owns d = 4L .. 4L+3 (two packed d-pairs).
    const int cb = warp * 8;
    ull w0d[8], w1d[8], w2d[8], bd[8], lwr[8][2];
    {
        const float4* lw4 = (const float4*)lin_w;
#pragma unroll
        for (int ch = 0; ch < 8; ++ch) {
            int c = cb + ch;
            float a0 = conv_w[3 * c + 0], a1 = conv_w[3 * c + 1], a2 = conv_w[3 * c + 2];
            float bb = conv_b[c];
            w0d[ch] = pack2(a0, a0);
            w1d[ch] = pack2(a1, a1);
            w2d[ch] = pack2(a2, a2);
            bd[ch]  = pack2(bb, bb);
            float4 A = lw4[c * 32 + lane];   // lw[c, 4L .. 4L+3]
            lwr[ch][0] = pack2(0.5f * A.x, 0.5f * A.y);   // relu trick pre-scale
            lwr[ch][1] = pack2(0.5f * A.z, 0.5f * A.w);
        }
    }

    const int stride = g_is64 ? 2 : 1;

    for (int e = (int)blockIdx.x; e < NEDGE; e += BLOCKS) {
        const int row = edge_idx[(size_t)stride * e];
        const int col = edge_idx[(size_t)stride * (NEDGE + e)];
        const int rel = edge_type[(size_t)stride * e];

        // Front-batched gathers: 3 x LDG.128, lane L gets d=4L..4L+3.
        float4 U = ((const float4*)(h + (size_t)row * D))[lane];
        float4 V = ((const float4*)(h + (size_t)col * D))[lane];
        float4 R = ((const float4*)(g + (size_t)rel * D))[lane];
        ull u0 = pack2(U.x, U.y), u1 = pack2(U.z, U.w);
        ull v0 = pack2(V.x, V.y), v1 = pack2(V.z, V.w);
        ull r0 = pack2(R.x, R.y), r1 = pack2(R.z, R.w);

        ull acc0 = 0ULL, acc1 = 0ULL;
#pragma unroll
        for (int ch = 0; ch < 8; ++ch) {
            ull t0 = ffma2(w2d[ch], r0, bd[ch]);
            ull t1 = ffma2(w2d[ch], r1, bd[ch]);
            t0 = ffma2(w1d[ch], v0, t0);
            t1 = ffma2(w1d[ch], v1, t1);
            t0 = ffma2(w0d[ch], u0, t0);
            t1 = ffma2(w0d[ch], u1, t1);
            t0 = relu2x2(t0);
            t1 = relu2x2(t1);
            acc0 = ffma2(t0, lwr[ch][0], acc0);
            acc1 = ffma2(t1, lwr[ch][1], acc1);
        }
        float2 a = unpack2(fadd2(acc0, acc1));
        float s = a.x + a.y;
#pragma unroll
        for (int off = 16; off > 0; off >>= 1)
            s += __shfl_xor_sync(0xffffffffu, s, off);
        if (lane == 0)
            atomicAdd(out + e, s);
    }
}

extern "C" void kernel_launch(void* const* d_in, const int* in_sizes, int n_in,
                              void* d_out, int out_size) {
    // Identify inputs by unique element counts (immune to metadata ordering).
    const float *h = 0, *g = 0, *conv_w = 0, *conv_b = 0, *lin_w = 0, *lin_b = 0;
    const int *edge_idx = 0, *edge_type = 0;
    for (int i = 0; i < n_in; ++i) {
        switch (in_sizes[i]) {
            case NEDGE * 128: h         = (const float*)d_in[i]; break;
            case 500 * 128:   g         = (const float*)d_in[i]; break;
            case 2 * NEDGE:   edge_idx  = (const int*)d_in[i];   break;
            case NEDGE:       edge_type = (const int*)d_in[i];   break;
            case 96:          conv_w    = (const float*)d_in[i]; break;
            case 32:          conv_b    = (const float*)d_in[i]; break;
            case 4096:        lin_w     = (const float*)d_in[i]; break;
            case 1:           lin_b     = (const float*)d_in[i]; break;
            default: break;
        }
    }
    float* out = (float*)d_out;

    init_kernel<<<(NEDGE + 255) / 256, 256>>>(out, lin_b, edge_idx);
    convkb_kernel<<<BLOCKS, THREADS>>>(h, g, edge_idx, edge_type,
                                       conv_w, conv_b, lin_w, out);
}

// round 9
// speedup vs baseline: 1.1999x; 1.0828x over previous
#include <cuda_runtime.h>

// ConvKB: score[e] = sum_{c,d} relu(w0c*u_d + w1c*v_d + w2c*r_d + bc) * lw[c,d] + lb
// Warp = (edge, 8 channels, all 128 d); 4 warps/block share an edge (gathers hit L1).
// 3-stage pipeline: idx staged 2 iters ahead, gathers 1 iter ahead -> latency chain
// (idx LDG -> gather LDG.128) fully overlapped by compute. Packed f32x2 FMA, relu
// via (t+|t|) with lw pre-scaled 0.5, shuffle reduce + atomicAdd into out=lin_b.

#define D 128
#define THREADS 128
#define BLOCKS 444            // 148 SMs * 3 blocks
#define NEDGE 50000

typedef unsigned long long ull;

__device__ int g_is64;        // 1 if index arrays are int64, 0 if int32

__device__ __forceinline__ ull ffma2(ull a, ull b, ull c) {
    ull d;
    asm("fma.rn.f32x2 %0, %1, %2, %3;" : "=l"(d) : "l"(a), "l"(b), "l"(c));
    return d;
}
__device__ __forceinline__ ull fadd2(ull a, ull b) {
    ull d;
    asm("add.rn.f32x2 %0, %1, %2;" : "=l"(d) : "l"(a), "l"(b));
    return d;
}
// 2*relu(a) packed: a + |a|
__device__ __forceinline__ ull relu2x2(ull a) {
    return fadd2(a, a & 0x7FFFFFFF7FFFFFFFULL);
}
__device__ __forceinline__ ull pack2(float lo, float hi) {
    ull d;
    asm("mov.b64 %0, {%1, %2};" : "=l"(d) : "f"(lo), "f"(hi));
    return d;
}
__device__ __forceinline__ float2 unpack2(ull v) {
    float2 r;
    asm("mov.b64 {%0, %1}, %2;" : "=f"(r.x), "=f"(r.y) : "l"(v));
    return r;
}

// Fused: dtype detection (thread 0) + out[] init to lin_b.
__global__ void init_kernel(float* __restrict__ out, const float* __restrict__ lin_b,
                            const int* __restrict__ ei) {
    int i = blockIdx.x * blockDim.x + threadIdx.x;
    if (i == 0) {
        int is64 = 1;
        for (int k = 1; k < 128; k += 2)
            if (ei[k] != 0) { is64 = 0; break; }
        g_is64 = is64;
    }
    if (i < NEDGE) out[i] = lin_b[0];
}

__global__ void __launch_bounds__(THREADS, 3) convkb_kernel(
    const float* __restrict__ h,
    const float* __restrict__ g,
    const int* __restrict__ edge_idx,    // [2,E], low int32 words read
    const int* __restrict__ edge_type,   // [E]
    const float* __restrict__ conv_w,    // [C,3]
    const float* __restrict__ conv_b,    // [C]
    const float* __restrict__ lin_w,     // [C*D]
    float* __restrict__ out)             // [E], pre-initialized to lin_b
{
    const int lane = threadIdx.x & 31;
    const int warp = threadIdx.x >> 5;

    // ---- Edge-invariant register state: warp covers channels cb..cb+7 ----
    // Lane L owns d = 4L .. 4L+3 (two packed d-pairs).
    const int cb = warp * 8;
    ull w0d[8], w1d[8], w2d[8], bd[8], lwr[8][2];
    {
        const float4* lw4 = (const float4*)lin_w;
#pragma unroll
        for (int ch = 0; ch < 8; ++ch) {
            int c = cb + ch;
            float a0 = conv_w[3 * c + 0], a1 = conv_w[3 * c + 1], a2 = conv_w[3 * c + 2];
            float bb = conv_b[c];
            w0d[ch] = pack2(a0, a0);
            w1d[ch] = pack2(a1, a1);
            w2d[ch] = pack2(a2, a2);
            bd[ch]  = pack2(bb, bb);
            float4 A = lw4[c * 32 + lane];   // lw[c, 4L .. 4L+3]
            lwr[ch][0] = pack2(0.5f * A.x, 0.5f * A.y);   // relu-trick pre-scale
            lwr[ch][1] = pack2(0.5f * A.z, 0.5f * A.w);
        }
    }

    const int stride = g_is64 ? 2 : 1;

    // ---- Pipeline prologue ----
    // Stage 0 data (edge e0), stage 1 indices (edge e0+G).
    int e = (int)blockIdx.x;                      // < NEDGE always (444 < 50000)
    float4 U, V, R;
    {
        int row = edge_idx[(size_t)stride * e];
        int col = edge_idx[(size_t)stride * (NEDGE + e)];
        int rel = edge_type[(size_t)stride * e];
        U = ((const float4*)(h + (size_t)row * D))[lane];
        V = ((const float4*)(h + (size_t)col * D))[lane];
        R = ((const float4*)(g + (size_t)rel * D))[lane];
    }
    int e1 = e + BLOCKS; if (e1 >= NEDGE) e1 = NEDGE - 1;   // clamp: safe, discarded
    int row1 = edge_idx[(size_t)stride * e1];
    int col1 = edge_idx[(size_t)stride * (NEDGE + e1)];
    int rel1 = edge_type[(size_t)stride * e1];

    for (; e < NEDGE; e += BLOCKS) {
        // Issue next edge's gathers (indices staged 2 iters ago -> ready).
        float4 NU = ((const float4*)(h + (size_t)row1 * D))[lane];
        float4 NV = ((const float4*)(h + (size_t)col1 * D))[lane];
        float4 NR = ((const float4*)(g + (size_t)rel1 * D))[lane];

        // Stage indices for e + 2*BLOCKS.
        int e2 = e + 2 * BLOCKS; if (e2 >= NEDGE) e2 = NEDGE - 1;
        int row2 = edge_idx[(size_t)stride * e2];
        int col2 = edge_idx[(size_t)stride * (NEDGE + e2)];
        int rel2 = edge_type[(size_t)stride * e2];

        // ---- Compute current edge ----
        ull u0 = pack2(U.x, U.y), u1 = pack2(U.z, U.w);
        ull v0 = pack2(V.x, V.y), v1 = pack2(V.z, V.w);
        ull r0 = pack2(R.x, R.y), r1 = pack2(R.z, R.w);

        ull acc0 = 0ULL, acc1 = 0ULL;
#pragma unroll
        for (int ch = 0; ch < 8; ++ch) {
            ull t0 = ffma2(w2d[ch], r0, bd[ch]);
            ull t1 = ffma2(w2d[ch], r1, bd[ch]);
            t0 = ffma2(w1d[ch], v0, t0);
            t1 = ffma2(w1d[ch], v1, t1);
            t0 = ffma2(w0d[ch], u0, t0);
            t1 = ffma2(w0d[ch], u1, t1);
            t0 = relu2x2(t0);
            t1 = relu2x2(t1);
            acc0 = ffma2(t0, lwr[ch][0], acc0);
            acc1 = ffma2(t1, lwr[ch][1], acc1);
        }
        float2 a = unpack2(fadd2(acc0, acc1));
        float s = a.x + a.y;
#pragma unroll
        for (int off = 16; off > 0; off >>= 1)
            s += __shfl_xor_sync(0xffffffffu, s, off);
        if (lane == 0)
            atomicAdd(out + e, s);

        // ---- Rotate pipeline ----
        U = NU; V = NV; R = NR;
        row1 = row2; col1 = col2; rel1 = rel2;
    }
}

extern "C" void kernel_launch(void* const* d_in, const int* in_sizes, int n_in,
                              void* d_out, int out_size) {
    // Identify inputs by unique element counts (immune to metadata ordering).
    const float *h = 0, *g = 0, *conv_w = 0, *conv_b = 0, *lin_w = 0, *lin_b = 0;
    const int *edge_idx = 0, *edge_type = 0;
    for (int i = 0; i < n_in; ++i) {
        switch (in_sizes[i]) {
            case NEDGE * 128: h         = (const float*)d_in[i]; break;
            case 500 * 128:   g         = (const float*)d_in[i]; break;
            case 2 * NEDGE:   edge_idx  = (const int*)d_in[i];   break;
            case NEDGE:       edge_type = (const int*)d_in[i];   break;
            case 96:          conv_w    = (const float*)d_in[i]; break;
            case 32:          conv_b    = (const float*)d_in[i]; break;
            case 4096:        lin_w     = (const float*)d_in[i]; break;
            case 1:           lin_b     = (const float*)d_in[i]; break;
            default: break;
        }
    }
    float* out = (float*)d_out;

    init_kernel<<<(NEDGE + 255) / 256, 256>>>(out, lin_b, edge_idx);
    convkb_kernel<<<BLOCKS, THREADS>>>(h, g, edge_idx, edge_type,
                                       conv_w, conv_b, lin_w, out);
}

// round 10
// speedup vs baseline: 1.2658x; 1.0549x over previous
#include <cuda_runtime.h>

// ConvKB: score[e] = sum_{c,d} relu(w0c*u_d + w1c*v_d + w2c*r_d + bc) * lw[c,d] + lb
// Warp = (edge, 8 channels, all 128 d); 4 warps/block share an edge (L1-hit gathers).
// 3-stage pipeline (idx staged 2 iters ahead, gathers 1 ahead) + unroll-2 so the
// compiler renames away rotate MOVs. Gathers load as ulonglong2 (pre-packed pairs).
// Packed f32x2 FMA, relu via (t+|t|) with lw pre-scaled 0.5, shuffle reduce +
// atomicAdd into out pre-initialized to lin_b.

#define D 128
#define THREADS 128
#define BLOCKS 444            // 148 SMs * 3 blocks
#define NEDGE 50000

typedef unsigned long long ull;

__device__ int g_is64;        // 1 if index arrays are int64, 0 if int32

__device__ __forceinline__ ull ffma2(ull a, ull b, ull c) {
    ull d;
    asm("fma.rn.f32x2 %0, %1, %2, %3;" : "=l"(d) : "l"(a), "l"(b), "l"(c));
    return d;
}
__device__ __forceinline__ ull fadd2(ull a, ull b) {
    ull d;
    asm("add.rn.f32x2 %0, %1, %2;" : "=l"(d) : "l"(a), "l"(b));
    return d;
}
// 2*relu(a) packed: a + |a|
__device__ __forceinline__ ull relu2x2(ull a) {
    return fadd2(a, a & 0x7FFFFFFF7FFFFFFFULL);
}
__device__ __forceinline__ ull pack2(float lo, float hi) {
    ull d;
    asm("mov.b64 %0, {%1, %2};" : "=l"(d) : "f"(lo), "f"(hi));
    return d;
}
__device__ __forceinline__ float2 unpack2(ull v) {
    float2 r;
    asm("mov.b64 {%0, %1}, %2;" : "=f"(r.x), "=f"(r.y) : "l"(v));
    return r;
}

// Fused: dtype detection (thread 0) + out[] init to lin_b.
__global__ void init_kernel(float* __restrict__ out, const float* __restrict__ lin_b,
                            const int* __restrict__ ei) {
    int i = blockIdx.x * blockDim.x + threadIdx.x;
    if (i == 0) {
        int is64 = 1;
        for (int k = 1; k < 128; k += 2)
            if (ei[k] != 0) { is64 = 0; break; }
        g_is64 = is64;
    }
    if (i < NEDGE) out[i] = lin_b[0];
}

__global__ void __launch_bounds__(THREADS, 3) convkb_kernel(
    const float* __restrict__ h,
    const float* __restrict__ g,
    const int* __restrict__ edge_idx,    // [2,E], low int32 words read
    const int* __restrict__ edge_type,   // [E]
    const float* __restrict__ conv_w,    // [C,3]
    const float* __restrict__ conv_b,    // [C]
    const float* __restrict__ lin_w,     // [C*D]
    float* __restrict__ out)             // [E], pre-initialized to lin_b
{
    const int lane = threadIdx.x & 31;
    const int warp = threadIdx.x >> 5;

    // ---- Edge-invariant register state: warp covers channels cb..cb+7 ----
    // Lane L owns d = 4L .. 4L+3 (two packed d-pairs).
    const int cb = warp * 8;
    ull w0d[8], w1d[8], w2d[8], bd[8], lwr[8][2];
    {
        const float4* lw4 = (const float4*)lin_w;
#pragma unroll
        for (int ch = 0; ch < 8; ++ch) {
            int c = cb + ch;
            float a0 = conv_w[3 * c + 0], a1 = conv_w[3 * c + 1], a2 = conv_w[3 * c + 2];
            float bb = conv_b[c];
            w0d[ch] = pack2(a0, a0);
            w1d[ch] = pack2(a1, a1);
            w2d[ch] = pack2(a2, a2);
            bd[ch]  = pack2(bb, bb);
            float4 A = lw4[c * 32 + lane];   // lw[c, 4L .. 4L+3]
            lwr[ch][0] = pack2(0.5f * A.x, 0.5f * A.y);   // relu-trick pre-scale
            lwr[ch][1] = pack2(0.5f * A.z, 0.5f * A.w);
        }
    }

    const int stride = g_is64 ? 2 : 1;

    // ---- Pipeline prologue: data for e0, indices for e0+BLOCKS ----
    int e = (int)blockIdx.x;                       // < NEDGE always
    ulonglong2 U, V, R;
    {
        int row = edge_idx[(size_t)stride * e];
        int col = edge_idx[(size_t)stride * (NEDGE + e)];
        int rel = edge_type[(size_t)stride * e];
        U = ((const ulonglong2*)(h + (size_t)row * D))[lane];
        V = ((const ulonglong2*)(h + (size_t)col * D))[lane];
        R = ((const ulonglong2*)(g + (size_t)rel * D))[lane];
    }
    int e1 = min(e + BLOCKS, NEDGE - 1);           // clamp: safe addr, discarded
    int row1 = edge_idx[(size_t)stride * e1];
    int col1 = edge_idx[(size_t)stride * (NEDGE + e1)];
    int rel1 = edge_type[(size_t)stride * e1];

#pragma unroll 2
    for (; e < NEDGE; e += BLOCKS) {
        // Issue next edge's gathers (indices staged last iteration).
        ulonglong2 NU = ((const ulonglong2*)(h + (size_t)row1 * D))[lane];
        ulonglong2 NV = ((const ulonglong2*)(h + (size_t)col1 * D))[lane];
        ulonglong2 NR = ((const ulonglong2*)(g + (size_t)rel1 * D))[lane];

        // Stage indices for e + 2*BLOCKS.
        int e2 = min(e + 2 * BLOCKS, NEDGE - 1);
        int row2 = edge_idx[(size_t)stride * e2];
        int col2 = edge_idx[(size_t)stride * (NEDGE + e2)];
        int rel2 = edge_type[(size_t)stride * e2];

        // ---- Compute current edge (data pre-packed as ull pairs) ----
        ull acc0 = 0ULL, acc1 = 0ULL;
#pragma unroll
        for (int ch = 0; ch < 8; ++ch) {
            ull t0 = ffma2(w2d[ch], R.x, bd[ch]);
            ull t1 = ffma2(w2d[ch], R.y, bd[ch]);
            t0 = ffma2(w1d[ch], V.x, t0);
            t1 = ffma2(w1d[ch], V.y, t1);
            t0 = ffma2(w0d[ch], U.x, t0);
            t1 = ffma2(w0d[ch], U.y, t1);
            t0 = relu2x2(t0);
            t1 = relu2x2(t1);
            acc0 = ffma2(t0, lwr[ch][0], acc0);
            acc1 = ffma2(t1, lwr[ch][1], acc1);
        }
        float2 a = unpack2(fadd2(acc0, acc1));
        float s = a.x + a.y;
#pragma unroll
        for (int off = 16; off > 0; off >>= 1)
            s += __shfl_xor_sync(0xffffffffu, s, off);
        if (lane == 0)
            atomicAdd(out + e, s);

        // ---- Rotate pipeline (renamed away by unroll-2) ----
        U = NU; V = NV; R = NR;
        row1 = row2; col1 = col2; rel1 = rel2;
    }
}

extern "C" void kernel_launch(void* const* d_in, const int* in_sizes, int n_in,
                              void* d_out, int out_size) {
    // Identify inputs by unique element counts (immune to metadata ordering).
    const float *h = 0, *g = 0, *conv_w = 0, *conv_b = 0, *lin_w = 0, *lin_b = 0;
    const int *edge_idx = 0, *edge_type = 0;
    for (int i = 0; i < n_in; ++i) {
        switch (in_sizes[i]) {
            case NEDGE * 128: h         = (const float*)d_in[i]; break;
            case 500 * 128:   g         = (const float*)d_in[i]; break;
            case 2 * NEDGE:   edge_idx  = (const int*)d_in[i];   break;
            case NEDGE:       edge_type = (const int*)d_in[i];   break;
            case 96:          conv_w    = (const float*)d_in[i]; break;
            case 32:          conv_b    = (const float*)d_in[i]; break;
            case 4096:        lin_w     = (const float*)d_in[i]; break;
            case 1:           lin_b     = (const float*)d_in[i]; break;
            default: break;
        }
    }
    float* out = (float*)d_out;

    init_kernel<<<(NEDGE + 255) / 256, 256>>>(out, lin_b, edge_idx);
    convkb_kernel<<<BLOCKS, THREADS>>>(h, g, edge_idx, edge_type,
                                       conv_w, conv_b, lin_w, out);
}